// round 1
// baseline (speedup 1.0000x reference)
#include <cuda_runtime.h>
#include <cstddef>

#define NUM_CLASSES 1000000
#define FEAT_DIM    128
#define BATCH       16384
#define ALPHA       0.5f

// Scratch: per-class partial sums (only rows for labels in the batch are ever
// touched/zeroed), per-class counts, and a double loss accumulator.
__device__ float  g_sums[(size_t)NUM_CLASSES * FEAT_DIM];  // 512 MB static, bss
__device__ float  g_counts[NUM_CLASSES];
__device__ double g_loss;

// ---------------------------------------------------------------------------
// K0: zero the scratch rows we will touch (one block per batch element).
// Duplicate labels race on writing 0 — benign.
// ---------------------------------------------------------------------------
__global__ void k_init(const int* __restrict__ labels)
{
    const int b = blockIdx.x;
    const int t = threadIdx.x;
    const int l = labels[b];
    g_sums[(size_t)l * FEAT_DIM + t] = 0.0f;
    if (t == 0) {
        g_counts[l] = 0.0f;
        if (b == 0) g_loss = 0.0;
    }
}

// ---------------------------------------------------------------------------
// K1: scatter features into per-class sums + counts, and accumulate the
// center-loss sum of squared diffs (block reduction -> double atomic).
// One block (128 threads) per batch element; thread t owns feature dim t.
// ---------------------------------------------------------------------------
__global__ void k_accum(const float* __restrict__ features,
                        const float* __restrict__ centers,
                        const int*   __restrict__ labels)
{
    const int b = blockIdx.x;
    const int t = threadIdx.x;
    const int l = labels[b];

    const float f = features[(size_t)b * FEAT_DIM + t];
    const float c = centers[(size_t)l * FEAT_DIM + t];

    atomicAdd(&g_sums[(size_t)l * FEAT_DIM + t], f);
    if (t == 0) atomicAdd(&g_counts[l], 1.0f);

    const float d = f - c;
    float v = d * d;

    // 128-thread block reduce: warp shuffle then 4-way shared combine.
    __shared__ float s[4];
    #pragma unroll
    for (int o = 16; o > 0; o >>= 1)
        v += __shfl_down_sync(0xffffffffu, v, o);
    if ((t & 31) == 0) s[t >> 5] = v;
    __syncthreads();
    if (t == 0) {
        const float tot = s[0] + s[1] + s[2] + s[3];
        atomicAdd(&g_loss, (double)tot);
    }
}

// ---------------------------------------------------------------------------
// K2 (after the bulk memcpy): overwrite the present rows with the momentum
// update, and emit the scalar loss. Duplicate labels write identical values.
// new_c = c + ALPHA * (mean - c);  mean = sum / max(count, 1)
// ---------------------------------------------------------------------------
__global__ void k_update(const float* __restrict__ centers,
                         const int*   __restrict__ labels,
                         float*       __restrict__ out)
{
    const int b = blockIdx.x;
    const int t = threadIdx.x;
    const int l = labels[b];

    const size_t idx = (size_t)l * FEAT_DIM + t;
    const float cnt  = g_counts[l];
    const float c    = centers[idx];
    const float mean = g_sums[idx] / fmaxf(cnt, 1.0f);

    out[1 + idx] = c + ALPHA * (mean - c);

    if (b == 0 && t == 0) {
        // loss = LAMBDA_C * sum_sq / (2 * B), LAMBDA_C = 1.0
        out[0] = (float)(g_loss / (2.0 * (double)BATCH));
    }
}

// ---------------------------------------------------------------------------
// Launch: init -> accumulate -> bulk D2D copy of centers into out[1..] ->
// overwrite present rows + loss. All stream-ordered, graph-capturable.
// ---------------------------------------------------------------------------
extern "C" void kernel_launch(void* const* d_in, const int* in_sizes, int n_in,
                              void* d_out, int out_size)
{
    const float* features = (const float*)d_in[0];   // [BATCH, FEAT_DIM]
    const float* centers  = (const float*)d_in[1];   // [NUM_CLASSES, FEAT_DIM]
    const int*   labels   = (const int*)d_in[2];     // [BATCH] (int32)
    float*       out      = (float*)d_out;           // [1 + NUM_CLASSES*FEAT_DIM]

    (void)in_sizes; (void)n_in; (void)out_size;

    k_init <<<BATCH, FEAT_DIM>>>(labels);
    k_accum<<<BATCH, FEAT_DIM>>>(features, centers, labels);

    // Bulk copy centers -> out[1:] (unchanged classes). Driver copy path
    // handles the 4-byte destination misalignment at full bandwidth.
    cudaMemcpyAsync(out + 1, centers,
                    (size_t)NUM_CLASSES * FEAT_DIM * sizeof(float),
                    cudaMemcpyDeviceToDevice);

    k_update<<<BATCH, FEAT_DIM>>>(centers, labels, out);
}

// round 3
// speedup vs baseline: 1.9709x; 1.9709x over previous
#include <cuda_runtime.h>
#include <cstddef>

#define NUM_CLASSES 1000000
#define FEAT_DIM    128
#define BATCH       16384
#define ALPHA       0.5f

#define N_ELEMS   ((size_t)NUM_CLASSES * FEAT_DIM)   // 128,000,000
#define N_QUADS   (N_ELEMS / 4)                       // 32,000,000

// Scratch: per-class partial sums (only rows for labels in the batch are ever
// touched), per-class counts, and a double loss accumulator.
__device__ float  g_sums[N_ELEMS];      // 512 MB static bss
__device__ float  g_counts[NUM_CLASSES];
__device__ double g_loss;

// ---------------------------------------------------------------------------
// K0: zero the scratch rows we will touch. One warp per batch element,
// lane k zeroes quad k of the class row (float4 stores).
// Duplicate labels race on writing 0 — benign.
// ---------------------------------------------------------------------------
__global__ void k_init(const int* __restrict__ labels)
{
    const int gid  = blockIdx.x * blockDim.x + threadIdx.x;
    const int w    = gid >> 5;          // batch element
    const int lane = gid & 31;
    if (w < BATCH) {
        const int l = labels[w];
        reinterpret_cast<float4*>(g_sums)[(size_t)l * 32 + lane] =
            make_float4(0.f, 0.f, 0.f, 0.f);
        if (lane == 0) g_counts[l] = 0.0f;
    }
    if (gid == 0) g_loss = 0.0;
}

// ---------------------------------------------------------------------------
// K1: scatter features into per-class sums + counts, accumulate loss.
// One warp per batch element; lane k owns feature quad k.
// ---------------------------------------------------------------------------
__global__ void k_accum(const float* __restrict__ features,
                        const float* __restrict__ centers,
                        const int*   __restrict__ labels)
{
    const int gid  = blockIdx.x * blockDim.x + threadIdx.x;
    const int w    = gid >> 5;
    const int lane = gid & 31;
    if (w >= BATCH) return;

    const int l = labels[w];
    const float4 f = reinterpret_cast<const float4*>(features)[(size_t)w * 32 + lane];
    const float4 c = reinterpret_cast<const float4*>(centers )[(size_t)l * 32 + lane];

    float* srow = g_sums + (size_t)l * FEAT_DIM + lane * 4;
    atomicAdd(srow + 0, f.x);
    atomicAdd(srow + 1, f.y);
    atomicAdd(srow + 2, f.z);
    atomicAdd(srow + 3, f.w);
    if (lane == 0) atomicAdd(&g_counts[l], 1.0f);

    const float dx = f.x - c.x, dy = f.y - c.y, dz = f.z - c.z, dw = f.w - c.w;
    float v = dx * dx + dy * dy + dz * dz + dw * dw;
    #pragma unroll
    for (int o = 16; o > 0; o >>= 1)
        v += __shfl_down_sync(0xffffffffu, v, o);
    if (lane == 0) atomicAdd(&g_loss, (double)v);
}

// ---------------------------------------------------------------------------
// K2: bulk shifted copy  out[1 + i] = centers[i]  with dst-ALIGNED float4
// stores. Thread j produces out quad j = {c[4j-1], c[4j], c[4j+1], c[4j+2]};
// the straddle element c[4j-1] comes from the warp neighbor via shfl_up
// (lane 0 scalar-loads it; that line is L1/L2-hot from the adjacent warp).
// Thread 0 writes the head out[1..3] and the tail out[N].
// Grid covers exactly N_QUADS threads (divisible by 256, all lanes active).
// ---------------------------------------------------------------------------
__global__ void k_copy(const float* __restrict__ c, float* __restrict__ out)
{
    const size_t j = (size_t)blockIdx.x * blockDim.x + threadIdx.x;  // dst quad
    const float4 b = reinterpret_cast<const float4*>(c)[j];

    float pw = __shfl_up_sync(0xffffffffu, b.w, 1);
    if ((threadIdx.x & 31) == 0 && j > 0)
        pw = c[4 * j - 1];

    if (j == 0) {
        out[1] = b.x; out[2] = b.y; out[3] = b.z;
        out[N_ELEMS] = c[N_ELEMS - 1];               // tail element
    } else {
        reinterpret_cast<float4*>(out)[j] = make_float4(pw, b.x, b.y, b.z);
    }
}

// ---------------------------------------------------------------------------
// K3: overwrite present rows with momentum update, emit loss.
// One warp per batch element (duplicates write identical values).
// new_c = (1-ALPHA)*c + (ALPHA/cnt)*sum
// ---------------------------------------------------------------------------
__global__ void k_update(const float* __restrict__ centers,
                         const int*   __restrict__ labels,
                         float*       __restrict__ out)
{
    const int gid  = blockIdx.x * blockDim.x + threadIdx.x;
    const int w    = gid >> 5;
    const int lane = gid & 31;
    if (w >= BATCH) return;

    const int l = labels[w];
    const float  cnt = g_counts[l];
    const float  k1  = 1.0f - ALPHA;
    const float  k2  = ALPHA / fmaxf(cnt, 1.0f);

    const size_t q = (size_t)l * 32 + lane;
    const float4 c = reinterpret_cast<const float4*>(centers)[q];
    const float4 s = reinterpret_cast<const float4*>(g_sums)[q];

    float* o = out + 1 + (size_t)l * FEAT_DIM + lane * 4;  // misaligned: scalar stores
    o[0] = k1 * c.x + k2 * s.x;
    o[1] = k1 * c.y + k2 * s.y;
    o[2] = k1 * c.z + k2 * s.z;
    o[3] = k1 * c.w + k2 * s.w;

    if (gid == 0)
        out[0] = (float)(g_loss / (2.0 * (double)BATCH));
}

// ---------------------------------------------------------------------------
extern "C" void kernel_launch(void* const* d_in, const int* in_sizes, int n_in,
                              void* d_out, int out_size)
{
    const float* features = (const float*)d_in[0];
    const float* centers  = (const float*)d_in[1];
    const int*   labels   = (const int*)d_in[2];
    float*       out      = (float*)d_out;

    (void)in_sizes; (void)n_in; (void)out_size;

    const int warps_grid = (BATCH * 32) / 256;          // 2048 blocks of 256

    k_init  <<<warps_grid, 256>>>(labels);
    k_accum <<<warps_grid, 256>>>(features, centers, labels);
    k_copy  <<<(int)(N_QUADS / 256), 256>>>(centers, out);   // 125,000 blocks
    k_update<<<warps_grid, 256>>>(centers, labels, out);
}